// round 16
// baseline (speedup 1.0000x reference)
#include <cuda_runtime.h>
#include <cuda_bf16.h>
#include <math.h>
#include <stdint.h>

#define BB 16
#define QQ 1024
#define TT 1024
#define DD 256
#define EPS 0.1f
#define INV_EPS 10.0f
#define N_ITERS 5
#define BIGNEG (-1e30f)
#define L2IE 14.426950408889634f      // 10 * log2(e)
#define EPSLN2 0.06931471805599453f   // 0.1 * ln(2)

#define K3 768
#define KC 64
#define STAGES 12
#define VZ 8              // v split-K factor

// ---------------- device scratch ----------------
__device__ float g_costp[(size_t)BB * QQ * TT];
__device__ __nv_bfloat16 g_A3[(size_t)BB * QQ * K3];
__device__ __nv_bfloat16 g_B3[(size_t)BB * TT * K3];
__device__ float g_u[BB * QQ];
__device__ float g_vp[BB * TT];
__device__ float g_vf[BB];
__device__ float g_vpm[BB * VZ * TT];
__device__ float g_vps[BB * VZ * TT];
__device__ float g_x2[BB * QQ];
__device__ float g_y2[BB * TT];
__device__ float g_y2p[BB * TT];
__device__ int g_pref[BB * TT];
__device__ int g_colidx[BB * TT];
__device__ int g_nf[BB];
__device__ int g_nfilt[BB];
__device__ int g_f0[BB];
__device__ float g_fc;
__device__ int g_tile_ctr;
__device__ int g_tcum[BB + 1];
__device__ int g_ntile_n[BB];
__device__ int g_total_tiles;

// ---------------- PTX helpers (baseline sm_80+) ----------------
__device__ __forceinline__ uint32_t smem_to_u32(const void* p) {
    uint32_t a;
    asm("{ .reg .u64 t; cvta.to.shared.u64 t, %1; cvt.u32.u64 %0, t; }"
        : "=r"(a) : "l"(p));
    return a;
}
#define CP_ASYNC16(dst, src) \
    asm volatile("cp.async.cg.shared.global [%0], [%1], 16;" :: "r"(dst), "l"(src))
#define CP_COMMIT() asm volatile("cp.async.commit_group;")
#define CP_WAIT1() asm volatile("cp.async.wait_group 1;")
#define CP_WAIT0() asm volatile("cp.async.wait_group 0;")

__device__ __forceinline__ void ldsm_x4(uint32_t& r0, uint32_t& r1, uint32_t& r2,
                                        uint32_t& r3, uint32_t addr) {
    asm volatile("ldmatrix.sync.aligned.m8n8.x4.shared.b16 {%0,%1,%2,%3}, [%4];"
                 : "=r"(r0), "=r"(r1), "=r"(r2), "=r"(r3) : "r"(addr));
}
__device__ __forceinline__ void mma16816(float* d, const uint32_t* a, const uint32_t* b) {
    asm volatile(
        "mma.sync.aligned.m16n8k16.row.col.f32.bf16.bf16.f32 "
        "{%0,%1,%2,%3}, {%4,%5,%6,%7}, {%8,%9}, {%0,%1,%2,%3};"
        : "+f"(d[0]), "+f"(d[1]), "+f"(d[2]), "+f"(d[3])
        : "r"(a[0]), "r"(a[1]), "r"(a[2]), "r"(a[3]), "r"(b[0]), "r"(b[1]));
}
// fast exp2/log2 via MUFU (no pre-multiply)
__device__ __forceinline__ float ex2f(float x) {
    float r;
    asm("ex2.approx.f32 %0, %1;" : "=f"(r) : "f"(x));
    return r;
}
__device__ __forceinline__ float lg2f(float x) {
    float r;
    asm("lg2.approx.f32 %0, %1;" : "=f"(r) : "f"(x));
    return r;
}
// log2-domain online-LSE merge
__device__ __forceinline__ void lse_merge2(float& m, float& s, float mc, float sc) {
    float M = fmaxf(m, mc);
    s = s * ex2f(m - M) + sc * ex2f(mc - M);
    m = M;
}
__device__ __forceinline__ uint32_t pack_bf2(__nv_bfloat16 a, __nv_bfloat16 b) {
    __nv_bfloat162 t{a, b};
    return *(uint32_t*)&t;
}

// ------- scan + init + pad fused: one block per batch, 1024 threads --------
__global__ void scan_pad_kernel(const float* __restrict__ filt) {
    const int b = blockIdx.x;
    const int t = threadIdx.x;
    const int w = t >> 5;
    const int lane = t & 31;
    __shared__ int woff[32];
    __shared__ int f0s;
    __shared__ int snf;
    if (t == 0) f0s = TT;
    __syncthreads();

    int flag = (filt[b * TT + t] <= 0.0f) ? 0 : 1;
    unsigned mask = __ballot_sync(0xffffffffu, flag);
    int lanep = __popc(mask & ((1u << lane) - 1u));
    if (lane == 0) woff[w] = __popc(mask);
    __syncthreads();
    if (w == 0) {
        int v = woff[lane];
        int orig = v;
#pragma unroll
        for (int o = 1; o < 32; o <<= 1) {
            int u2 = __shfl_up_sync(0xffffffffu, v, o);
            if (lane >= o) v += u2;
        }
        woff[lane] = v - orig;
        if (lane == 31) snf = v;
    }
    __syncthreads();
    int excl = woff[w] + lanep;
    g_pref[b * TT + t] = excl;
    if (flag) g_colidx[b * TT + excl] = t;
    else atomicMin(&f0s, t);
    const int nf = snf;
    if (t == 1023) {
        g_nf[b] = nf;
        g_nfilt[b] = TT - nf;
    }
    __syncthreads();
    if (t == 0) {
        g_f0[b] = f0s;
        g_vf[b] = 0.0f;
    }
    g_vp[b * TT + t] = 0.0f;

    const int nfpad = (nf + 127) & ~127;
    const float INF = __int_as_float(0x7f800000);
    uint4 z = make_uint4(0u, 0u, 0u, 0u);
    for (int idx = t; idx < (nfpad - nf) * 96; idx += 1024) {
        int r = nf + idx / 96;
        int c = (idx % 96) * 8;
        *(uint4*)(g_B3 + ((size_t)(b * TT + r)) * K3 + c) = z;
    }
    for (int j = nf + t; j < nfpad; j += 1024) g_y2p[b * TT + j] = INF;
}

// ------- split fp32 -> bf16 hi/lo (3-pass) + row norms; warp/row -----
__global__ void split_norms_kernel(const float* __restrict__ preds,
                                   const float* __restrict__ tgts,
                                   const float* __restrict__ filt) {
    int gw = (blockIdx.x * blockDim.x + threadIdx.x) >> 5;
    int lane = threadIdx.x & 31;
    if (gw >= 2 * BB * QQ) return;
    bool isA = gw < BB * QQ;
    int r = isA ? gw : gw - BB * QQ;
    const float* src = (isA ? preds : tgts) + (size_t)r * DD;

    bool kept = true;
    __nv_bfloat16* dst;
    if (isA) {
        dst = g_A3 + (size_t)r * K3;
    } else {
        kept = filt[r] > 0.0f;
        int b = r >> 10;
        dst = g_B3 + ((size_t)(b * TT + g_pref[r])) * K3;
    }

    int k0 = lane * 4;
    int k1 = 128 + lane * 4;
    float4 x0 = *(const float4*)(src + k0);
    float4 x1 = *(const float4*)(src + k1);

    float s = 0.0f;
    s = fmaf(x0.x, x0.x, s); s = fmaf(x0.y, x0.y, s);
    s = fmaf(x0.z, x0.z, s); s = fmaf(x0.w, x0.w, s);
    s = fmaf(x1.x, x1.x, s); s = fmaf(x1.y, x1.y, s);
    s = fmaf(x1.z, x1.z, s); s = fmaf(x1.w, x1.w, s);

    if (kept) {
#pragma unroll
        for (int i = 0; i < 2; i++) {
            float4 x = i ? x1 : x0;
            int k = i ? k1 : k0;
            __nv_bfloat16 hx = __float2bfloat16_rn(x.x);
            __nv_bfloat16 hy = __float2bfloat16_rn(x.y);
            __nv_bfloat16 hz = __float2bfloat16_rn(x.z);
            __nv_bfloat16 hw = __float2bfloat16_rn(x.w);
            __nv_bfloat16 lx = __float2bfloat16_rn(x.x - __bfloat162float(hx));
            __nv_bfloat16 ly = __float2bfloat16_rn(x.y - __bfloat162float(hy));
            __nv_bfloat16 lz = __float2bfloat16_rn(x.z - __bfloat162float(hz));
            __nv_bfloat16 lw = __float2bfloat16_rn(x.w - __bfloat162float(hw));
            uint2 hp = make_uint2(pack_bf2(hx, hy), pack_bf2(hz, hw));
            uint2 lp = make_uint2(pack_bf2(lx, ly), pack_bf2(lz, lw));
            *(uint2*)(dst + 0 * DD + k) = hp;
            *(uint2*)(dst + 1 * DD + k) = isA ? lp : hp;
            *(uint2*)(dst + 2 * DD + k) = isA ? hp : lp;
        }
    }
#pragma unroll
    for (int o = 16; o > 0; o >>= 1) s += __shfl_xor_sync(0xffffffffu, s, o);
    if (lane == 0) {
        if (isA) {
            g_x2[r] = s;
        } else {
            g_y2[r] = s;
            if (kept) {
                int b = r >> 10;
                g_y2p[b * TT + g_pref[r]] = s;
            }
        }
    }
}

// ------- fc: upper bound 2*(max|x| + max|y|) + tile table + counter --------
__global__ void fc_kernel() {
    const int tid = threadIdx.x;
    float mx = 0.0f, my = 0.0f;
    for (int i = tid; i < BB * QQ; i += 1024) {
        mx = fmaxf(mx, g_x2[i]);
        my = fmaxf(my, g_y2[i]);
    }
    __shared__ float sx[32], sy[32];
#pragma unroll
    for (int o = 16; o > 0; o >>= 1) {
        mx = fmaxf(mx, __shfl_xor_sync(0xffffffffu, mx, o));
        my = fmaxf(my, __shfl_xor_sync(0xffffffffu, my, o));
    }
    if ((tid & 31) == 0) { sx[tid >> 5] = mx; sy[tid >> 5] = my; }
    __syncthreads();
    if (tid == 0) {
        float MX = sx[0], MY = sy[0];
#pragma unroll
        for (int i = 1; i < 32; i++) { MX = fmaxf(MX, sx[i]); MY = fmaxf(MY, sy[i]); }
        g_fc = 2.0f * (sqrtf(MX) + sqrtf(MY));
        int c = 0;
        for (int b = 0; b < BB; b++) {
            g_tcum[b] = c;
            int nt = ((g_nf[b] + 127) & ~127) >> 7;
            g_ntile_n[b] = nt;
            c += nt * (QQ / 128);
        }
        g_tcum[BB] = c;
        g_total_tiles = c;
        g_tile_ctr = 0;
    }
}

// --------- cost GEMM: persistent CTAs over exact tile list ------------------
#define SM_TOTAL 65536
__global__ void __launch_bounds__(256)
cost_mma_kernel() {
    extern __shared__ char smem[];
    const uint32_t sb = smem_to_u32(smem);
    const int tid = threadIdx.x;
    const int wid = tid >> 5;
    const int lane = tid & 31;
    const int warp_m = wid >> 2;
    const int warp_n = wid & 3;

    __shared__ int s_tile;
    const int total = g_total_tiles;

    const int laneA_r = (lane & 7) + ((lane >> 3) & 1) * 8;
    const int khA = (lane >> 4) & 1;
    const int laneB_r = (lane & 7) + ((lane >> 4) & 1) * 8;
    const int khB = (lane >> 3) & 1;
    const int xorA = laneA_r & 7;
    const int xorB = laneB_r & 7;

    for (;;) {
        if (tid == 0) s_tile = atomicAdd(&g_tile_ctr, 1);
        __syncthreads();
        const int t = s_tile;
        if (t >= total) return;

        int b = 0;
        while (t >= g_tcum[b + 1]) b++;
        const int local = t - g_tcum[b];
        const int ntn = g_ntile_n[b];
        const int mt = local / ntn;
        const int nt = local - mt * ntn;
        const int m_base = mt * 128;
        const int n_base = nt * 128;

        const __nv_bfloat16* Ag = g_A3 + (size_t)(b * QQ + m_base) * K3;
        const __nv_bfloat16* Bg = g_B3 + (size_t)(b * TT + n_base) * K3;

        auto load_stage = [&](int s, int buf) {
            uint32_t abase = sb + (uint32_t)buf * 32768u;
            uint32_t bbase = abase + 16384u;
#pragma unroll
            for (int v = 0; v < 4; v++) {
                int idx = tid + v * 256;
                int r = idx >> 3;
                int g = idx & 7;
                uint32_t off = (uint32_t)(r * 128 + ((g ^ (r & 7)) << 4));
                CP_ASYNC16(abase + off, Ag + (size_t)r * K3 + s * KC + g * 8);
                CP_ASYNC16(bbase + off, Bg + (size_t)r * K3 + s * KC + g * 8);
            }
        };

        float acc[4][4][4];
#pragma unroll
        for (int i = 0; i < 4; i++)
#pragma unroll
            for (int j = 0; j < 4; j++)
#pragma unroll
                for (int e = 0; e < 4; e++) acc[i][j][e] = 0.0f;

        uint32_t fa[2][4][4];
        uint32_t fb[2][4][2];

        auto ldfrag = [&](uint32_t abase, uint32_t bbase, int kq, int buf) {
#pragma unroll
            for (int im = 0; im < 4; im++) {
                int row = warp_m * 64 + im * 16 + laneA_r;
                uint32_t addr = abase + (uint32_t)(row * 128 + (((khA + 2 * kq) ^ xorA) << 4));
                ldsm_x4(fa[buf][im][0], fa[buf][im][1], fa[buf][im][2], fa[buf][im][3], addr);
            }
#pragma unroll
            for (int ip = 0; ip < 2; ip++) {
                int row = warp_n * 32 + ip * 16 + laneB_r;
                uint32_t addr = bbase + (uint32_t)(row * 128 + (((khB + 2 * kq) ^ xorB) << 4));
                ldsm_x4(fb[buf][ip * 2][0], fb[buf][ip * 2][1],
                        fb[buf][ip * 2 + 1][0], fb[buf][ip * 2 + 1][1], addr);
            }
        };

        load_stage(0, 0);
        CP_COMMIT();

        for (int s = 0; s < STAGES; s++) {
            const int buf = s & 1;
            if (s + 1 < STAGES) {
                load_stage(s + 1, buf ^ 1);
                CP_COMMIT();
                CP_WAIT1();
            } else {
                CP_WAIT0();
            }
            __syncthreads();

            uint32_t abase = sb + (uint32_t)buf * 32768u;
            uint32_t bbase = abase + 16384u;

            ldfrag(abase, bbase, 0, 0);
#pragma unroll
            for (int kq = 0; kq < 4; kq++) {
                const int cur = kq & 1;
                if (kq < 3) ldfrag(abase, bbase, kq + 1, cur ^ 1);
#pragma unroll
                for (int im = 0; im < 4; im++)
#pragma unroll
                    for (int in = 0; in < 4; in++)
                        mma16816(acc[im][in], fa[cur][im], fb[cur][in]);
            }
            __syncthreads();
        }

        const float* x2p = g_x2 + b * QQ + m_base;
        const float* y2p = g_y2p + b * TT + n_base;
#pragma unroll
        for (int im = 0; im < 4; im++) {
            int m0 = warp_m * 64 + im * 16 + (lane >> 2);
            float xi0 = x2p[m0];
            float xi1 = x2p[m0 + 8];
#pragma unroll
            for (int in = 0; in < 4; in++) {
                int n0 = warp_n * 32 + in * 8 + (lane & 3) * 2;
                float y0 = y2p[n0];
                float y1 = y2p[n0 + 1];
                float c00 = sqrtf(fmaxf(fmaf(-2.0f, acc[im][in][0], xi0 + y0), 0.0f));
                float c01 = sqrtf(fmaxf(fmaf(-2.0f, acc[im][in][1], xi0 + y1), 0.0f));
                float c10 = sqrtf(fmaxf(fmaf(-2.0f, acc[im][in][2], xi1 + y0), 0.0f));
                float c11 = sqrtf(fmaxf(fmaf(-2.0f, acc[im][in][3], xi1 + y1), 0.0f));
                size_t g0 = ((size_t)(b * QQ + m_base + m0)) * TT + n_base + n0;
                size_t g1 = ((size_t)(b * QQ + m_base + m0 + 8)) * TT + n_base + n0;
                *(float2*)(g_costp + g0) = make_float2(c00, c01);
                *(float2*)(g_costp + g1) = make_float2(c10, c11);
            }
        }
        __syncthreads();
    }
}

// ---------------- u update: 8 rows per block, log2-domain -------------------
__global__ void u_update_p() {
    const int row0 = blockIdx.x * 8;
    const int b = row0 >> 10;
    const int tid = threadIdx.x;
    const int w = tid >> 5;
    const int lane = tid & 31;
    const int nf = g_nf[b];
    const int nfpad = (nf + 127) & ~127;
    const int nk = nfpad >> 7;
    const float fc = g_fc;
    const float vf = g_vf[b];
    const float nfl = (float)g_nfilt[b];

    __shared__ float svp[1024];
    for (int j = tid; j < nfpad; j += 256) svp[j] = g_vp[b * TT + j] * L2IE;
    __syncthreads();

    const int row = row0 + w;
    const float* crow = g_costp + (size_t)row * TT;

    float m = BIGNEG, s = 0.0f;
    int k = 0;
    for (; k + 1 < nk; k += 2) {
        int j0 = k * 128 + lane * 4;
        int j1 = j0 + 128;
        float4 c0 = *(const float4*)(crow + j0);
        float4 c1 = *(const float4*)(crow + j1);
        float4 v0 = *(const float4*)(svp + j0);
        float4 v1 = *(const float4*)(svp + j1);
        float a0 = fmaf(-L2IE, c0.x, v0.x), a1 = fmaf(-L2IE, c0.y, v0.y);
        float a2 = fmaf(-L2IE, c0.z, v0.z), a3 = fmaf(-L2IE, c0.w, v0.w);
        float b0 = fmaf(-L2IE, c1.x, v1.x), b1 = fmaf(-L2IE, c1.y, v1.y);
        float b2 = fmaf(-L2IE, c1.z, v1.z), b3 = fmaf(-L2IE, c1.w, v1.w);
        float mc = fmaxf(fmaxf(fmaxf(a0, a1), fmaxf(a2, a3)),
                         fmaxf(fmaxf(b0, b1), fmaxf(b2, b3)));
        mc = fmaxf(mc, BIGNEG);
        float sc = ex2f(a0 - mc) + ex2f(a1 - mc) + ex2f(a2 - mc) + ex2f(a3 - mc) +
                   ex2f(b0 - mc) + ex2f(b1 - mc) + ex2f(b2 - mc) + ex2f(b3 - mc);
        lse_merge2(m, s, mc, sc);
    }
    if (k < nk) {
        int j0 = k * 128 + lane * 4;
        float4 c0 = *(const float4*)(crow + j0);
        float4 v0 = *(const float4*)(svp + j0);
        float a0 = fmaf(-L2IE, c0.x, v0.x), a1 = fmaf(-L2IE, c0.y, v0.y);
        float a2 = fmaf(-L2IE, c0.z, v0.z), a3 = fmaf(-L2IE, c0.w, v0.w);
        float mc = fmaxf(fmaxf(fmaxf(a0, a1), fmaxf(a2, a3)), BIGNEG);
        float sc = ex2f(a0 - mc) + ex2f(a1 - mc) + ex2f(a2 - mc) + ex2f(a3 - mc);
        lse_merge2(m, s, mc, sc);
    }
#pragma unroll
    for (int o = 16; o > 0; o >>= 1) {
        float m2 = __shfl_xor_sync(0xffffffffu, m, o);
        float s2 = __shfl_xor_sync(0xffffffffu, s, o);
        lse_merge2(m, s, m2, s2);
    }
    lse_merge2(m, s, (vf - fc) * L2IE, nfl);
    if (lane == 0) g_u[row] = -EPSLN2 * (lg2f(s) + m);
}

// -------- v partial: grid (8, BB, VZ), block (32,8); log2-domain ------------
__global__ void v_partial() {
    const int b = blockIdx.y;
    const int z = blockIdx.z;
    const int lane = threadIdx.x;
    const int wy = threadIdx.y;
    const int nfpad = (g_nf[b] + 127) & ~127;
    const int jb = blockIdx.x * 128;
    if (jb >= nfpad) return;
    const int j = jb + lane * 4;
    const float* base = g_costp + ((size_t)b * QQ) * TT;

    __shared__ float su[128];
    if (threadIdx.y < 4) {
        int q = threadIdx.y * 32 + lane;
        su[q] = g_u[b * QQ + z * 128 + q] * L2IE;
    }
    __syncthreads();

    float m[4] = {BIGNEG, BIGNEG, BIGNEG, BIGNEG};
    float s[4] = {0.0f, 0.0f, 0.0f, 0.0f};

    for (int q0 = wy * 8; q0 < 128; q0 += 64) {
        float4 c[8];
        float uu[8];
#pragma unroll
        for (int r = 0; r < 8; r++) {
            c[r] = *(const float4*)(base + (size_t)(z * 128 + q0 + r) * TT + j);
            uu[r] = su[q0 + r];
        }
#pragma unroll
        for (int e = 0; e < 4; e++) {
            float a[8];
#pragma unroll
            for (int r = 0; r < 8; r++) {
                float ce = (e == 0) ? c[r].x : (e == 1) ? c[r].y : (e == 2) ? c[r].z : c[r].w;
                a[r] = fmaf(-L2IE, ce, uu[r]);
            }
            float mc = a[0];
#pragma unroll
            for (int r = 1; r < 8; r++) mc = fmaxf(mc, a[r]);
            mc = fmaxf(mc, BIGNEG);
            float sc = 0.0f;
#pragma unroll
            for (int r = 0; r < 8; r++) sc += ex2f(a[r] - mc);
            lse_merge2(m[e], s[e], mc, sc);
        }
    }

    __shared__ float sm[8][128];
    __shared__ float ss[8][128];
#pragma unroll
    for (int e = 0; e < 4; e++) {
        sm[wy][lane * 4 + e] = m[e];
        ss[wy][lane * 4 + e] = s[e];
    }
    __syncthreads();
    if (wy < 4) {
        int li = wy * 32 + lane;
        float M = sm[0][li], S = ss[0][li];
#pragma unroll
        for (int w = 1; w < 8; w++) lse_merge2(M, S, sm[w][li], ss[w][li]);
        size_t po = ((size_t)(b * VZ + z)) * TT + jb + li;
        g_vpm[po] = M;
        g_vps[po] = S;
    }
}

// ------- v merge (+ vf for block x==0): log2-domain -------------------------
__global__ void v_merge_vf() {
    const int b = blockIdx.y;
    const int tid = threadIdx.x;
    const int jj = blockIdx.x * 256 + tid;
    if (jj < g_nf[b]) {
        float M = BIGNEG, S = 0.0f;
#pragma unroll
        for (int z = 0; z < VZ; z++) {
            size_t po = ((size_t)(b * VZ + z)) * TT + jj;
            lse_merge2(M, S, g_vpm[po], g_vps[po]);
        }
        g_vp[b * TT + jj] = -EPSLN2 * (lg2f(S) + M);
    }
    if (blockIdx.x == 0) {
        const float* ub = g_u + b * QQ;
        __shared__ float sh8[8];
        float4 u4 = *(const float4*)(ub + tid * 4);
        float a0 = u4.x * L2IE, a1 = u4.y * L2IE;
        float a2 = u4.z * L2IE, a3 = u4.w * L2IE;
        float m = fmaxf(fmaxf(a0, a1), fmaxf(a2, a3));
#pragma unroll
        for (int o = 16; o > 0; o >>= 1) m = fmaxf(m, __shfl_xor_sync(0xffffffffu, m, o));
        int w = tid >> 5;
        if ((tid & 31) == 0) sh8[w] = m;
        __syncthreads();
        float M = sh8[0];
#pragma unroll
        for (int i = 1; i < 8; i++) M = fmaxf(M, sh8[i]);
        __syncthreads();
        float s = ex2f(a0 - M) + ex2f(a1 - M) + ex2f(a2 - M) + ex2f(a3 - M);
#pragma unroll
        for (int o = 16; o > 0; o >>= 1) s += __shfl_xor_sync(0xffffffffu, s, o);
        if ((tid & 31) == 0) sh8[w] = s;
        __syncthreads();
        if (tid == 0) {
            float S = sh8[0];
#pragma unroll
            for (int i = 1; i < 8; i++) S += sh8[i];
            g_vf[b] = -EPSLN2 * (lg2f(S) + M) + g_fc;
        }
    }
}

// ---------------- final: unpack P row + argmax (first max) ----------------
__global__ void p_argmax_kernel(float* __restrict__ outP,
                                float* __restrict__ outIdx) {
    const int row = blockIdx.x;
    const int b = row >> 10;
    const int tid = threadIdx.x;
    const float* crow = g_costp + (size_t)row * TT;
    const float* vp = g_vp + b * TT;
    const int* cidx = g_colidx + b * TT;
    const int nf = g_nf[b];
    const int nfilt = g_nfilt[b];
    const int f0 = g_f0[b];
    const float fc = g_fc;
    const float vf = g_vf[b];
    const float u = g_u[row];
    const float pconst = ex2f((u + vf - fc) * L2IE);

    __shared__ float rowbuf[1024];
    __shared__ float sv[256];
    __shared__ int si[256];

#pragma unroll
    for (int i = 0; i < 4; i++) rowbuf[tid + i * 256] = pconst;
    __syncthreads();

    float best = BIGNEG;
    int bidx = 0x7fffffff;
#pragma unroll
    for (int i = 0; i < 4; i++) {
        int j = tid + i * 256;
        if (j < nf) {
            float p = ex2f((u + vp[j] - crow[j]) * L2IE);
            int t = cidx[j];
            rowbuf[t] = p;
            if (p > best || (p == best && t < bidx)) { best = p; bidx = t; }
        }
    }
    sv[tid] = best;
    si[tid] = bidx;
    __syncthreads();
#pragma unroll
    for (int st = 128; st > 0; st >>= 1) {
        if (tid < st) {
            float v2 = sv[tid + st];
            int i2 = si[tid + st];
            if (v2 > sv[tid] || (v2 == sv[tid] && i2 < si[tid])) {
                sv[tid] = v2;
                si[tid] = i2;
            }
        }
        __syncthreads();
    }

    if (outP) {
#pragma unroll
        for (int i = 0; i < 2; i++) {
            int j4 = (tid + i * 256) * 2;
            float2 o = make_float2(rowbuf[j4], rowbuf[j4 + 1]);
            *(float2*)(outP + (size_t)row * TT + j4) = o;
        }
    }
    if (tid == 0 && outIdx) {
        float bv = sv[0];
        int bi = si[0];
        if (nfilt > 0) {
            if (pconst > bv || (pconst == bv && f0 < bi)) { bv = pconst; bi = f0; }
        }
        outIdx[row] = (float)bi;
    }
}

// ---------------- launch ----------------
extern "C" void kernel_launch(void* const* d_in, const int* in_sizes, int n_in,
                              void* d_out, int out_size) {
    const float* preds = (const float*)d_in[0];
    const float* tgts = (const float*)d_in[1];
    const float* filt = (const float*)d_in[2];
    float* out = (float*)d_out;

    const int NP = BB * QQ * TT;
    const int NI = BB * QQ;
    float* outIdx = nullptr;
    float* outP = nullptr;
    if (out_size == NP + NI) { outIdx = out; outP = out + NI; }
    else if (out_size == NP) { outP = out; }
    else if (out_size == NI) { outIdx = out; }
    else { outIdx = out; outP = out + NI; }

    cudaFuncSetAttribute(cost_mma_kernel,
                         cudaFuncAttributeMaxDynamicSharedMemorySize, SM_TOTAL);

    scan_pad_kernel<<<BB, 1024>>>(filt);
    {
        const int nwarps = 2 * BB * QQ;
        split_norms_kernel<<<(nwarps * 32 + 255) / 256, 256>>>(preds, tgts, filt);
    }
    fc_kernel<<<1, 1024>>>();
    cost_mma_kernel<<<148, 256, SM_TOTAL>>>();
    for (int it = 0; it < N_ITERS; it++) {
        u_update_p<<<BB * QQ / 8, 256>>>();
        v_partial<<<dim3(TT / 128, BB, VZ), dim3(32, 8)>>>();
        v_merge_vf<<<dim3(TT / 256, BB), 256>>>();
    }
    p_argmax_kernel<<<BB * QQ, 256>>>(outP, outIdx);
}

// round 17
// speedup vs baseline: 1.7590x; 1.7590x over previous
#include <cuda_runtime.h>
#include <cuda_bf16.h>
#include <math.h>
#include <stdint.h>

#define BB 16
#define QQ 1024
#define TT 1024
#define DD 256
#define EPS 0.1f
#define INV_EPS 10.0f
#define N_ITERS 5
#define BIGNEG (-1e30f)
#define L2IE 14.426950408889634f      // 10 * log2(e)
#define EPSLN2 0.06931471805599453f   // 0.1 * ln(2)

#define K3 768
#define KC 64
#define STAGES 12
#define VZ 8              // v split-K factor

// ---------------- device scratch ----------------
__device__ float g_costp[(size_t)BB * QQ * TT];
__device__ __nv_bfloat16 g_A3[(size_t)BB * QQ * K3];
__device__ __nv_bfloat16 g_B3[(size_t)BB * TT * K3];
__device__ float g_u[BB * QQ];
__device__ float g_vp[BB * TT];
__device__ float g_vf[BB];
__device__ float g_vpm[BB * VZ * TT];
__device__ float g_vps[BB * VZ * TT];
__device__ float g_x2[BB * QQ];
__device__ float g_y2[BB * TT];
__device__ float g_y2p[BB * TT];
__device__ int g_pref[BB * TT];
__device__ int g_colidx[BB * TT];
__device__ int g_nf[BB];
__device__ int g_nfilt[BB];
__device__ int g_f0[BB];
__device__ float g_fc;

// ---------------- PTX helpers (baseline sm_80+) ----------------
__device__ __forceinline__ uint32_t smem_to_u32(const void* p) {
    uint32_t a;
    asm("{ .reg .u64 t; cvta.to.shared.u64 t, %1; cvt.u32.u64 %0, t; }"
        : "=r"(a) : "l"(p));
    return a;
}
#define CP_ASYNC16(dst, src) \
    asm volatile("cp.async.cg.shared.global [%0], [%1], 16;" :: "r"(dst), "l"(src))
#define CP_COMMIT() asm volatile("cp.async.commit_group;")
#define CP_WAIT1() asm volatile("cp.async.wait_group 1;")
#define CP_WAIT0() asm volatile("cp.async.wait_group 0;")

__device__ __forceinline__ void ldsm_x4(uint32_t& r0, uint32_t& r1, uint32_t& r2,
                                        uint32_t& r3, uint32_t addr) {
    asm volatile("ldmatrix.sync.aligned.m8n8.x4.shared.b16 {%0,%1,%2,%3}, [%4];"
                 : "=r"(r0), "=r"(r1), "=r"(r2), "=r"(r3) : "r"(addr));
}
__device__ __forceinline__ void mma16816(float* d, const uint32_t* a, const uint32_t* b) {
    asm volatile(
        "mma.sync.aligned.m16n8k16.row.col.f32.bf16.bf16.f32 "
        "{%0,%1,%2,%3}, {%4,%5,%6,%7}, {%8,%9}, {%0,%1,%2,%3};"
        : "+f"(d[0]), "+f"(d[1]), "+f"(d[2]), "+f"(d[3])
        : "r"(a[0]), "r"(a[1]), "r"(a[2]), "r"(a[3]), "r"(b[0]), "r"(b[1]));
}
// fast exp2/log2 via MUFU, FTZ variants (same units __expf uses)
__device__ __forceinline__ float ex2f(float x) {
    float r;
    asm("ex2.approx.ftz.f32 %0, %1;" : "=f"(r) : "f"(x));
    return r;
}
__device__ __forceinline__ float lg2f(float x) {
    float r;
    asm("lg2.approx.ftz.f32 %0, %1;" : "=f"(r) : "f"(x));
    return r;
}
// log2-domain online-LSE merge
__device__ __forceinline__ void lse_merge2(float& m, float& s, float mc, float sc) {
    float M = fmaxf(m, mc);
    s = s * ex2f(m - M) + sc * ex2f(mc - M);
    m = M;
}
__device__ __forceinline__ uint32_t pack_bf2(__nv_bfloat16 a, __nv_bfloat16 b) {
    __nv_bfloat162 t{a, b};
    return *(uint32_t*)&t;
}

// ------- scan + init + pad fused: one block per batch, 1024 threads --------
__global__ void scan_pad_kernel(const float* __restrict__ filt) {
    const int b = blockIdx.x;
    const int t = threadIdx.x;
    const int w = t >> 5;
    const int lane = t & 31;
    __shared__ int woff[32];
    __shared__ int f0s;
    __shared__ int snf;
    if (t == 0) f0s = TT;
    __syncthreads();

    int flag = (filt[b * TT + t] <= 0.0f) ? 0 : 1;
    unsigned mask = __ballot_sync(0xffffffffu, flag);
    int lanep = __popc(mask & ((1u << lane) - 1u));
    if (lane == 0) woff[w] = __popc(mask);
    __syncthreads();
    if (w == 0) {
        int v = woff[lane];
        int orig = v;
#pragma unroll
        for (int o = 1; o < 32; o <<= 1) {
            int u2 = __shfl_up_sync(0xffffffffu, v, o);
            if (lane >= o) v += u2;
        }
        woff[lane] = v - orig;
        if (lane == 31) snf = v;
    }
    __syncthreads();
    int excl = woff[w] + lanep;
    g_pref[b * TT + t] = excl;
    if (flag) g_colidx[b * TT + excl] = t;
    else atomicMin(&f0s, t);
    const int nf = snf;
    if (t == 1023) {
        g_nf[b] = nf;
        g_nfilt[b] = TT - nf;
    }
    __syncthreads();
    if (t == 0) {
        g_f0[b] = f0s;
        g_vf[b] = 0.0f;
    }
    g_vp[b * TT + t] = 0.0f;

    const int nfpad = (nf + 127) & ~127;
    const float INF = __int_as_float(0x7f800000);
    uint4 z = make_uint4(0u, 0u, 0u, 0u);
    for (int idx = t; idx < (nfpad - nf) * 96; idx += 1024) {
        int r = nf + idx / 96;
        int c = (idx % 96) * 8;
        *(uint4*)(g_B3 + ((size_t)(b * TT + r)) * K3 + c) = z;
    }
    for (int j = nf + t; j < nfpad; j += 1024) g_y2p[b * TT + j] = INF;
}

// ------- split fp32 -> bf16 hi/lo (3-pass) + row norms; warp/row -----
__global__ void split_norms_kernel(const float* __restrict__ preds,
                                   const float* __restrict__ tgts,
                                   const float* __restrict__ filt) {
    int gw = (blockIdx.x * blockDim.x + threadIdx.x) >> 5;
    int lane = threadIdx.x & 31;
    if (gw >= 2 * BB * QQ) return;
    bool isA = gw < BB * QQ;
    int r = isA ? gw : gw - BB * QQ;
    const float* src = (isA ? preds : tgts) + (size_t)r * DD;

    bool kept = true;
    __nv_bfloat16* dst;
    if (isA) {
        dst = g_A3 + (size_t)r * K3;
    } else {
        kept = filt[r] > 0.0f;
        int b = r >> 10;
        dst = g_B3 + ((size_t)(b * TT + g_pref[r])) * K3;
    }

    int k0 = lane * 4;
    int k1 = 128 + lane * 4;
    float4 x0 = *(const float4*)(src + k0);
    float4 x1 = *(const float4*)(src + k1);

    float s = 0.0f;
    s = fmaf(x0.x, x0.x, s); s = fmaf(x0.y, x0.y, s);
    s = fmaf(x0.z, x0.z, s); s = fmaf(x0.w, x0.w, s);
    s = fmaf(x1.x, x1.x, s); s = fmaf(x1.y, x1.y, s);
    s = fmaf(x1.z, x1.z, s); s = fmaf(x1.w, x1.w, s);

    if (kept) {
#pragma unroll
        for (int i = 0; i < 2; i++) {
            float4 x = i ? x1 : x0;
            int k = i ? k1 : k0;
            __nv_bfloat16 hx = __float2bfloat16_rn(x.x);
            __nv_bfloat16 hy = __float2bfloat16_rn(x.y);
            __nv_bfloat16 hz = __float2bfloat16_rn(x.z);
            __nv_bfloat16 hw = __float2bfloat16_rn(x.w);
            __nv_bfloat16 lx = __float2bfloat16_rn(x.x - __bfloat162float(hx));
            __nv_bfloat16 ly = __float2bfloat16_rn(x.y - __bfloat162float(hy));
            __nv_bfloat16 lz = __float2bfloat16_rn(x.z - __bfloat162float(hz));
            __nv_bfloat16 lw = __float2bfloat16_rn(x.w - __bfloat162float(hw));
            uint2 hp = make_uint2(pack_bf2(hx, hy), pack_bf2(hz, hw));
            uint2 lp = make_uint2(pack_bf2(lx, ly), pack_bf2(lz, lw));
            *(uint2*)(dst + 0 * DD + k) = hp;
            *(uint2*)(dst + 1 * DD + k) = isA ? lp : hp;
            *(uint2*)(dst + 2 * DD + k) = isA ? hp : lp;
        }
    }
#pragma unroll
    for (int o = 16; o > 0; o >>= 1) s += __shfl_xor_sync(0xffffffffu, s, o);
    if (lane == 0) {
        if (isA) {
            g_x2[r] = s;
        } else {
            g_y2[r] = s;
            if (kept) {
                int b = r >> 10;
                g_y2p[b * TT + g_pref[r]] = s;
            }
        }
    }
}

// ---------------- fc: upper bound 2*(max|x| + max|y|) ----------------
__global__ void fc_kernel() {
    const int tid = threadIdx.x;
    float mx = 0.0f, my = 0.0f;
    for (int i = tid; i < BB * QQ; i += 1024) {
        mx = fmaxf(mx, g_x2[i]);
        my = fmaxf(my, g_y2[i]);
    }
    __shared__ float sx[32], sy[32];
#pragma unroll
    for (int o = 16; o > 0; o >>= 1) {
        mx = fmaxf(mx, __shfl_xor_sync(0xffffffffu, mx, o));
        my = fmaxf(my, __shfl_xor_sync(0xffffffffu, my, o));
    }
    if ((tid & 31) == 0) { sx[tid >> 5] = mx; sy[tid >> 5] = my; }
    __syncthreads();
    if (tid == 0) {
        float MX = sx[0], MY = sy[0];
#pragma unroll
        for (int i = 1; i < 32; i++) { MX = fmaxf(MX, sx[i]); MY = fmaxf(MY, sy[i]); }
        g_fc = 2.0f * (sqrtf(MX) + sqrtf(MY));
    }
}

// --------- cost GEMM (kept cols): 128x128 tile, 2-stage smem + frag dbuf ----
#define SM_TOTAL 65536
__global__ void __launch_bounds__(256)
cost_mma_kernel() {
    const int b = blockIdx.z;
    const int nfpad = (g_nf[b] + 127) & ~127;
    const int n_base = blockIdx.x * 128;
    if (n_base >= nfpad) return;

    extern __shared__ char smem[];
    const uint32_t sb = smem_to_u32(smem);
    const int m_base = blockIdx.y * 128;
    const int tid = threadIdx.x;
    const int wid = tid >> 5;
    const int lane = tid & 31;
    const int warp_m = wid >> 2;
    const int warp_n = wid & 3;

    const __nv_bfloat16* Ag = g_A3 + (size_t)(b * QQ + m_base) * K3;
    const __nv_bfloat16* Bg = g_B3 + (size_t)(b * TT + n_base) * K3;

    auto load_stage = [&](int s, int buf) {
        uint32_t abase = sb + (uint32_t)buf * 32768u;
        uint32_t bbase = abase + 16384u;
#pragma unroll
        for (int v = 0; v < 4; v++) {
            int idx = tid + v * 256;
            int r = idx >> 3;
            int g = idx & 7;
            uint32_t off = (uint32_t)(r * 128 + ((g ^ (r & 7)) << 4));
            CP_ASYNC16(abase + off, Ag + (size_t)r * K3 + s * KC + g * 8);
            CP_ASYNC16(bbase + off, Bg + (size_t)r * K3 + s * KC + g * 8);
        }
    };

    const int laneA_r = (lane & 7) + ((lane >> 3) & 1) * 8;
    const int khA = (lane >> 4) & 1;
    const int laneB_r = (lane & 7) + ((lane >> 4) & 1) * 8;
    const int khB = (lane >> 3) & 1;
    const int xorA = laneA_r & 7;
    const int xorB = laneB_r & 7;

    float acc[4][4][4];
#pragma unroll
    for (int i = 0; i < 4; i++)
#pragma unroll
        for (int j = 0; j < 4; j++)
#pragma unroll
            for (int e = 0; e < 4; e++) acc[i][j][e] = 0.0f;

    uint32_t fa[2][4][4];
    uint32_t fb[2][4][2];

    auto ldfrag = [&](uint32_t abase, uint32_t bbase, int kq, int buf) {
#pragma unroll
        for (int im = 0; im < 4; im++) {
            int row = warp_m * 64 + im * 16 + laneA_r;
            uint32_t addr = abase + (uint32_t)(row * 128 + (((khA + 2 * kq) ^ xorA) << 4));
            ldsm_x4(fa[buf][im][0], fa[buf][im][1], fa[buf][im][2], fa[buf][im][3], addr);
        }
#pragma unroll
        for (int ip = 0; ip < 2; ip++) {
            int row = warp_n * 32 + ip * 16 + laneB_r;
            uint32_t addr = bbase + (uint32_t)(row * 128 + (((khB + 2 * kq) ^ xorB) << 4));
            ldsm_x4(fb[buf][ip * 2][0], fb[buf][ip * 2][1],
                    fb[buf][ip * 2 + 1][0], fb[buf][ip * 2 + 1][1], addr);
        }
    };

    load_stage(0, 0);
    CP_COMMIT();

    for (int s = 0; s < STAGES; s++) {
        const int buf = s & 1;
        if (s + 1 < STAGES) {
            load_stage(s + 1, buf ^ 1);
            CP_COMMIT();
            CP_WAIT1();
        } else {
            CP_WAIT0();
        }
        __syncthreads();

        uint32_t abase = sb + (uint32_t)buf * 32768u;
        uint32_t bbase = abase + 16384u;

        ldfrag(abase, bbase, 0, 0);
#pragma unroll
        for (int kq = 0; kq < 4; kq++) {
            const int cur = kq & 1;
            if (kq < 3) ldfrag(abase, bbase, kq + 1, cur ^ 1);
#pragma unroll
            for (int im = 0; im < 4; im++)
#pragma unroll
                for (int in = 0; in < 4; in++)
                    mma16816(acc[im][in], fa[cur][im], fb[cur][in]);
        }
        __syncthreads();
    }

    // ----- epilogue: direct register -> global stores (packed columns) -----
    const float* x2p = g_x2 + b * QQ + m_base;
    const float* y2p = g_y2p + b * TT + n_base;
#pragma unroll
    for (int im = 0; im < 4; im++) {
        int m0 = warp_m * 64 + im * 16 + (lane >> 2);
        float xi0 = x2p[m0];
        float xi1 = x2p[m0 + 8];
#pragma unroll
        for (int in = 0; in < 4; in++) {
            int n0 = warp_n * 32 + in * 8 + (lane & 3) * 2;
            float y0 = y2p[n0];
            float y1 = y2p[n0 + 1];
            float c00 = sqrtf(fmaxf(fmaf(-2.0f, acc[im][in][0], xi0 + y0), 0.0f));
            float c01 = sqrtf(fmaxf(fmaf(-2.0f, acc[im][in][1], xi0 + y1), 0.0f));
            float c10 = sqrtf(fmaxf(fmaf(-2.0f, acc[im][in][2], xi1 + y0), 0.0f));
            float c11 = sqrtf(fmaxf(fmaf(-2.0f, acc[im][in][3], xi1 + y1), 0.0f));
            size_t g0 = ((size_t)(b * QQ + m_base + m0)) * TT + n_base + n0;
            size_t g1 = ((size_t)(b * QQ + m_base + m0 + 8)) * TT + n_base + n0;
            *(float2*)(g_costp + g0) = make_float2(c00, c01);
            *(float2*)(g_costp + g1) = make_float2(c10, c11);
        }
    }
}

// ---------------- u update: 8 rows per block, log2-domain (FTZ) -------------
__global__ void u_update_p() {
    const int row0 = blockIdx.x * 8;
    const int b = row0 >> 10;
    const int tid = threadIdx.x;
    const int w = tid >> 5;
    const int lane = tid & 31;
    const int nf = g_nf[b];
    const int nfpad = (nf + 127) & ~127;
    const int nk = nfpad >> 7;
    const float fc = g_fc;
    const float vf = g_vf[b];
    const float nfl = (float)g_nfilt[b];

    __shared__ float svp[1024];
    for (int j = tid; j < nfpad; j += 256) svp[j] = g_vp[b * TT + j] * L2IE;
    __syncthreads();

    const int row = row0 + w;
    const float* crow = g_costp + (size_t)row * TT;

    float m = BIGNEG, s = 0.0f;
    int k = 0;
    for (; k + 1 < nk; k += 2) {
        int j0 = k * 128 + lane * 4;
        int j1 = j0 + 128;
        float4 c0 = *(const float4*)(crow + j0);
        float4 c1 = *(const float4*)(crow + j1);
        float4 v0 = *(const float4*)(svp + j0);
        float4 v1 = *(const float4*)(svp + j1);
        float a0 = fmaf(-L2IE, c0.x, v0.x), a1 = fmaf(-L2IE, c0.y, v0.y);
        float a2 = fmaf(-L2IE, c0.z, v0.z), a3 = fmaf(-L2IE, c0.w, v0.w);
        float b0 = fmaf(-L2IE, c1.x, v1.x), b1 = fmaf(-L2IE, c1.y, v1.y);
        float b2 = fmaf(-L2IE, c1.z, v1.z), b3 = fmaf(-L2IE, c1.w, v1.w);
        float mc = fmaxf(fmaxf(fmaxf(a0, a1), fmaxf(a2, a3)),
                         fmaxf(fmaxf(b0, b1), fmaxf(b2, b3)));
        mc = fmaxf(mc, BIGNEG);
        float sc = ex2f(a0 - mc) + ex2f(a1 - mc) + ex2f(a2 - mc) + ex2f(a3 - mc) +
                   ex2f(b0 - mc) + ex2f(b1 - mc) + ex2f(b2 - mc) + ex2f(b3 - mc);
        lse_merge2(m, s, mc, sc);
    }
    if (k < nk) {
        int j0 = k * 128 + lane * 4;
        float4 c0 = *(const float4*)(crow + j0);
        float4 v0 = *(const float4*)(svp + j0);
        float a0 = fmaf(-L2IE, c0.x, v0.x), a1 = fmaf(-L2IE, c0.y, v0.y);
        float a2 = fmaf(-L2IE, c0.z, v0.z), a3 = fmaf(-L2IE, c0.w, v0.w);
        float mc = fmaxf(fmaxf(fmaxf(a0, a1), fmaxf(a2, a3)), BIGNEG);
        float sc = ex2f(a0 - mc) + ex2f(a1 - mc) + ex2f(a2 - mc) + ex2f(a3 - mc);
        lse_merge2(m, s, mc, sc);
    }
#pragma unroll
    for (int o = 16; o > 0; o >>= 1) {
        float m2 = __shfl_xor_sync(0xffffffffu, m, o);
        float s2 = __shfl_xor_sync(0xffffffffu, s, o);
        lse_merge2(m, s, m2, s2);
    }
    lse_merge2(m, s, (vf - fc) * L2IE, nfl);
    if (lane == 0) g_u[row] = -EPSLN2 * (lg2f(s) + m);
}

// -------- v partial: grid (8, BB, VZ), block (32,8); log2-domain (FTZ) ------
__global__ void v_partial() {
    const int b = blockIdx.y;
    const int z = blockIdx.z;
    const int lane = threadIdx.x;
    const int wy = threadIdx.y;
    const int nfpad = (g_nf[b] + 127) & ~127;
    const int jb = blockIdx.x * 128;
    if (jb >= nfpad) return;
    const int j = jb + lane * 4;
    const float* base = g_costp + ((size_t)b * QQ) * TT;

    __shared__ float su[128];
    if (threadIdx.y < 4) {
        int q = threadIdx.y * 32 + lane;
        su[q] = g_u[b * QQ + z * 128 + q] * L2IE;
    }
    __syncthreads();

    float m[4] = {BIGNEG, BIGNEG, BIGNEG, BIGNEG};
    float s[4] = {0.0f, 0.0f, 0.0f, 0.0f};

    for (int q0 = wy * 8; q0 < 128; q0 += 64) {
        float4 c[8];
        float uu[8];
#pragma unroll
        for (int r = 0; r < 8; r++) {
            c[r] = *(const float4*)(base + (size_t)(z * 128 + q0 + r) * TT + j);
            uu[r] = su[q0 + r];
        }
#pragma unroll
        for (int e = 0; e < 4; e++) {
            float a[8];
#pragma unroll
            for (int r = 0; r < 8; r++) {
                float ce = (e == 0) ? c[r].x : (e == 1) ? c[r].y : (e == 2) ? c[r].z : c[r].w;
                a[r] = fmaf(-L2IE, ce, uu[r]);
            }
            float mc = a[0];
#pragma unroll
            for (int r = 1; r < 8; r++) mc = fmaxf(mc, a[r]);
            mc = fmaxf(mc, BIGNEG);
            float sc = 0.0f;
#pragma unroll
            for (int r = 0; r < 8; r++) sc += ex2f(a[r] - mc);
            lse_merge2(m[e], s[e], mc, sc);
        }
    }

    __shared__ float sm[8][128];
    __shared__ float ss[8][128];
#pragma unroll
    for (int e = 0; e < 4; e++) {
        sm[wy][lane * 4 + e] = m[e];
        ss[wy][lane * 4 + e] = s[e];
    }
    __syncthreads();
    if (wy < 4) {
        int li = wy * 32 + lane;
        float M = sm[0][li], S = ss[0][li];
#pragma unroll
        for (int w = 1; w < 8; w++) lse_merge2(M, S, sm[w][li], ss[w][li]);
        size_t po = ((size_t)(b * VZ + z)) * TT + jb + li;
        g_vpm[po] = M;
        g_vps[po] = S;
    }
}

// ------- v merge (+ vf for block x==0): log2-domain (FTZ) -------------------
__global__ void v_merge_vf() {
    const int b = blockIdx.y;
    const int tid = threadIdx.x;
    const int jj = blockIdx.x * 256 + tid;
    if (jj < g_nf[b]) {
        float M = BIGNEG, S = 0.0f;
#pragma unroll
        for (int z = 0; z < VZ; z++) {
            size_t po = ((size_t)(b * VZ + z)) * TT + jj;
            lse_merge2(M, S, g_vpm[po], g_vps[po]);
        }
        g_vp[b * TT + jj] = -EPSLN2 * (lg2f(S) + M);
    }
    if (blockIdx.x == 0) {
        const float* ub = g_u + b * QQ;
        __shared__ float sh8[8];
        float4 u4 = *(const float4*)(ub + tid * 4);
        float a0 = u4.x * L2IE, a1 = u4.y * L2IE;
        float a2 = u4.z * L2IE, a3 = u4.w * L2IE;
        float m = fmaxf(fmaxf(a0, a1), fmaxf(a2, a3));
#pragma unroll
        for (int o = 16; o > 0; o >>= 1) m = fmaxf(m, __shfl_xor_sync(0xffffffffu, m, o));
        int w = tid >> 5;
        if ((tid & 31) == 0) sh8[w] = m;
        __syncthreads();
        float M = sh8[0];
#pragma unroll
        for (int i = 1; i < 8; i++) M = fmaxf(M, sh8[i]);
        __syncthreads();
        float s = ex2f(a0 - M) + ex2f(a1 - M) + ex2f(a2 - M) + ex2f(a3 - M);
#pragma unroll
        for (int o = 16; o > 0; o >>= 1) s += __shfl_xor_sync(0xffffffffu, s, o);
        if ((tid & 31) == 0) sh8[w] = s;
        __syncthreads();
        if (tid == 0) {
            float S = sh8[0];
#pragma unroll
            for (int i = 1; i < 8; i++) S += sh8[i];
            g_vf[b] = -EPSLN2 * (lg2f(S) + M) + g_fc;
        }
    }
}

// ---------------- final: unpack P row + argmax (first max) ----------------
__global__ void p_argmax_kernel(float* __restrict__ outP,
                                float* __restrict__ outIdx) {
    const int row = blockIdx.x;
    const int b = row >> 10;
    const int tid = threadIdx.x;
    const float* crow = g_costp + (size_t)row * TT;
    const float* vp = g_vp + b * TT;
    const int* cidx = g_colidx + b * TT;
    const int nf = g_nf[b];
    const int nfilt = g_nfilt[b];
    const int f0 = g_f0[b];
    const float fc = g_fc;
    const float vf = g_vf[b];
    const float u = g_u[row];
    const float pconst = ex2f((u + vf - fc) * L2IE);

    __shared__ float rowbuf[1024];
    __shared__ float sv[256];
    __shared__ int si[256];

#pragma unroll
    for (int i = 0; i < 4; i++) rowbuf[tid + i * 256] = pconst;
    __syncthreads();

    float best = BIGNEG;
    int bidx = 0x7fffffff;
#pragma unroll
    for (int i = 0; i < 4; i++) {
        int j = tid + i * 256;
        if (j < nf) {
            float p = ex2f((u + vp[j] - crow[j]) * L2IE);
            int t = cidx[j];
            rowbuf[t] = p;
            if (p > best || (p == best && t < bidx)) { best = p; bidx = t; }
        }
    }
    sv[tid] = best;
    si[tid] = bidx;
    __syncthreads();
#pragma unroll
    for (int st = 128; st > 0; st >>= 1) {
        if (tid < st) {
            float v2 = sv[tid + st];
            int i2 = si[tid + st];
            if (v2 > sv[tid] || (v2 == sv[tid] && i2 < si[tid])) {
                sv[tid] = v2;
                si[tid] = i2;
            }
        }
        __syncthreads();
    }

    if (outP) {
#pragma unroll
        for (int i = 0; i < 2; i++) {
            int j4 = (tid + i * 256) * 2;
            float2 o = make_float2(rowbuf[j4], rowbuf[j4 + 1]);
            *(float2*)(outP + (size_t)row * TT + j4) = o;
        }
    }
    if (tid == 0 && outIdx) {
        float bv = sv[0];
        int bi = si[0];
        if (nfilt > 0) {
            if (pconst > bv || (pconst == bv && f0 < bi)) { bv = pconst; bi = f0; }
        }
        outIdx[row] = (float)bi;
    }
}

// ---------------- launch ----------------
extern "C" void kernel_launch(void* const* d_in, const int* in_sizes, int n_in,
                              void* d_out, int out_size) {
    const float* preds = (const float*)d_in[0];
    const float* tgts = (const float*)d_in[1];
    const float* filt = (const float*)d_in[2];
    float* out = (float*)d_out;

    const int NP = BB * QQ * TT;
    const int NI = BB * QQ;
    float* outIdx = nullptr;
    float* outP = nullptr;
    if (out_size == NP + NI) { outIdx = out; outP = out + NI; }
    else if (out_size == NP) { outP = out; }
    else if (out_size == NI) { outIdx = out; }
    else { outIdx = out; outP = out + NI; }

    cudaFuncSetAttribute(cost_mma_kernel,
                         cudaFuncAttributeMaxDynamicSharedMemorySize, SM_TOTAL);

    scan_pad_kernel<<<BB, 1024>>>(filt);
    {
        const int nwarps = 2 * BB * QQ;
        split_norms_kernel<<<(nwarps * 32 + 255) / 256, 256>>>(preds, tgts, filt);
    }
    fc_kernel<<<1, 1024>>>();
    cost_mma_kernel<<<dim3(TT / 128, QQ / 128, BB), 256, SM_TOTAL>>>();
    for (int it = 0; it < N_ITERS; it++) {
        u_update_p<<<BB * QQ / 8, 256>>>();
        v_partial<<<dim3(TT / 128, BB, VZ), dim3(32, 8)>>>();
        v_merge_vf<<<dim3(TT / 256, BB), 256>>>();
    }
    p_argmax_kernel<<<BB * QQ, 256>>>(outP, outIdx);
}